// round 10
// baseline (speedup 1.0000x reference)
#include <cuda_runtime.h>
#include <cstdint>

// 2-layer LSTM, H=6, F=6, B=4096, T=1024.
// 2 elems/warp, 12 active lanes/elem: lane (l,k) owns hidden k of layer l,
// computes all 4 gate rows, K-dimension packed f32x2.
// Recurrence via register shuffles with per-lane sources (NO smem h-exchange,
// NO per-step syncwarp):
//   gather A: src = e*16 + l*6 + j  -> own-layer recurrent h (used directly)
//   gather B: src = e*16 + j        -> h0 (layer1's input; layer0 FSELs x)
// x staged per 16-step chunk in smem (one syncwarp per chunk boundary).
// Pipelined: main step m computes layer0(t=m) and layer1(t=m-1).
// Activations: tanh.approx; sigmoid = 0.5*tanh(z/2)+0.5 folded into weights.

#define WARPS_PER_BLOCK 14
#define THREADS (WARPS_PER_BLOCK * 32)
#define T_LEN 1024
#define TCHUNK 16
#define NCHUNK (T_LEN / TCHUNK)     // 64
#define CSTRIDE 104                 // floats per elem per chunk (96 data + 8 pad)
#define CSTRIDE4 (CSTRIDE / 4)      // 26

typedef unsigned long long ull;

__device__ __forceinline__ float tanha(float x) {
    float y; asm("tanh.approx.f32 %0, %1;" : "=f"(y) : "f"(x)); return y;
}
__device__ __forceinline__ ull pk2(float lo, float hi) {
    ull r; asm("mov.b64 %0, {%1, %2};" : "=l"(r) : "f"(lo), "f"(hi)); return r;
}
__device__ __forceinline__ void upk2(float& lo, float& hi, ull v) {
    asm("mov.b64 {%0, %1}, %2;" : "=f"(lo), "=f"(hi) : "l"(v));
}
__device__ __forceinline__ ull fma2(ull a, ull b, ull c) {
    ull d; asm("fma.rn.f32x2 %0, %1, %2, %3;" : "=l"(d) : "l"(a), "l"(b), "l"(c));
    return d;
}
__device__ __forceinline__ ull lds64(uint32_t addr) {
    ull v; asm volatile("ld.shared.b64 %0, [%1];" : "=l"(v) : "r"(addr));
    return v;
}

__global__ __launch_bounds__(THREADS, 1)
void lstm2_kernel(const float* __restrict__ x,
                  const float* __restrict__ wih0, const float* __restrict__ whh0,
                  const float* __restrict__ bih0, const float* __restrict__ bhh0,
                  const float* __restrict__ wih1, const float* __restrict__ whh1,
                  const float* __restrict__ bih1, const float* __restrict__ bhh1,
                  float* __restrict__ out, int B)
{
    __shared__ float sx[2][WARPS_PER_BLOCK][2 * CSTRIDE];
    __shared__ float soB[WARPS_PER_BLOCK][2 * CSTRIDE];

    const int lane = threadIdx.x & 31;
    const int warp = threadIdx.x >> 5;
    const int e    = lane >> 4;
    const int s    = lane & 15;
    const int l    = (s >= 6 && s < 12) ? 1 : 0;
    const int k    = (s < 6) ? s : ((s < 12) ? s - 6 : 0);
    const bool wr  = (s >= 6 && s < 12);

    const int b0 = (blockIdx.x * WARPS_PER_BLOCK + warp) * 2;
    if (b0 >= B) return;

    const int vb = e * 16;          // shfl base: h0 of own element
    const int rb = vb + l * 6;      // shfl base: own-layer recurrent h

    // ---- K-packed per-lane weights (4 gate rows of hidden k, layer l) ----
    const float* wih = l ? wih1 : wih0;
    const float* whh = l ? whh1 : whh0;
    const float* bih = l ? bih1 : bih0;
    const float* bhh = l ? bhh1 : bhh0;

    ull wx[4][3], wh[4][3], bz[4];
#pragma unroll
    for (int g = 0; g < 4; g++) {
        const float sc = (g == 2) ? 1.0f : 0.5f;
        const int row = g * 6 + k;
#pragma unroll
        for (int p = 0; p < 3; p++) {
            wx[g][p] = pk2(wih[row * 6 + 2 * p] * sc, wih[row * 6 + 2 * p + 1] * sc);
            wh[g][p] = pk2(whh[row * 6 + 2 * p] * sc, whh[row * 6 + 2 * p + 1] * sc);
        }
        bz[g] = pk2((bih[row] + bhh[row]) * sc, 0.0f);
    }

    uint32_t sx_u[2];
    sx_u[0] = (uint32_t)__cvta_generic_to_shared(&sx[0][warp][0]);
    sx_u[1] = (uint32_t)__cvta_generic_to_shared(&sx[1][warp][0]);

    float h = 0.0f, cc = 0.0f;

    auto stage = [&](int c, int buf) {
        float4* dst = reinterpret_cast<float4*>(sx[buf][warp]);
#pragma unroll
        for (int i = 0; i < 2; i++) {
            int idx = i * 32 + lane;              // 48 float4 total
            if (idx < 48) {
                int ee  = idx / 24;
                int off = idx - ee * 24;
                const float4* src = reinterpret_cast<const float4*>(
                    x + (size_t)(b0 + ee) * (T_LEN * 6) + c * (TCHUNK * 6));
                dst[ee * CSTRIDE4 + off] = src[off];
            }
        }
    };

    // one step: ia = smem address of the 6 x floats (layer0's input)
    auto step = [&](uint32_t ia, int dt) {
        // x pairs (meaningful for l=0 lanes; harmless broadcast for others)
        const ull xp0 = lds64(ia), xp1 = lds64(ia + 8), xp2 = lds64(ia + 16);

        // register gathers of previous-step h
        float r0a = __shfl_sync(0xffffffffu, h, rb + 0);
        float r0b = __shfl_sync(0xffffffffu, h, rb + 1);
        float r1a = __shfl_sync(0xffffffffu, h, rb + 2);
        float r1b = __shfl_sync(0xffffffffu, h, rb + 3);
        float r2a = __shfl_sync(0xffffffffu, h, rb + 4);
        float r2b = __shfl_sync(0xffffffffu, h, rb + 5);
        float h0a = __shfl_sync(0xffffffffu, h, vb + 0);
        float h0b = __shfl_sync(0xffffffffu, h, vb + 1);
        float h1a = __shfl_sync(0xffffffffu, h, vb + 2);
        float h1b = __shfl_sync(0xffffffffu, h, vb + 3);
        float h2a = __shfl_sync(0xffffffffu, h, vb + 4);
        float h2b = __shfl_sync(0xffffffffu, h, vb + 5);

        const ull r0 = pk2(r0a, r0b), r1 = pk2(r1a, r1b), r2 = pk2(r2a, r2b);
        // v = layer1 ? h0 pairs : x pairs
        const ull v0 = l ? pk2(h0a, h0b) : xp0;
        const ull v1 = l ? pk2(h1a, h1b) : xp1;
        const ull v2 = l ? pk2(h2a, h2b) : xp2;

        ull z0 = fma2(wx[0][0], v0, bz[0]);
        ull z1 = fma2(wx[1][0], v0, bz[1]);
        ull z2 = fma2(wx[2][0], v0, bz[2]);
        ull z3 = fma2(wx[3][0], v0, bz[3]);
        z0 = fma2(wx[0][1], v1, z0); z1 = fma2(wx[1][1], v1, z1);
        z2 = fma2(wx[2][1], v1, z2); z3 = fma2(wx[3][1], v1, z3);
        z0 = fma2(wx[0][2], v2, z0); z1 = fma2(wx[1][2], v2, z1);
        z2 = fma2(wx[2][2], v2, z2); z3 = fma2(wx[3][2], v2, z3);
        z0 = fma2(wh[0][0], r0, z0); z1 = fma2(wh[1][0], r0, z1);
        z2 = fma2(wh[2][0], r0, z2); z3 = fma2(wh[3][0], r0, z3);
        z0 = fma2(wh[0][1], r1, z0); z1 = fma2(wh[1][1], r1, z1);
        z2 = fma2(wh[2][1], r1, z2); z3 = fma2(wh[3][1], r1, z3);
        z0 = fma2(wh[0][2], r2, z0); z1 = fma2(wh[1][2], r2, z1);
        z2 = fma2(wh[2][2], r2, z2); z3 = fma2(wh[3][2], r2, z3);

        float a, b2;
        upk2(a, b2, z0); const float zi = a + b2;
        upk2(a, b2, z1); const float zf = a + b2;
        upk2(a, b2, z2); const float zg = a + b2;
        upk2(a, b2, z3); const float zo = a + b2;

        const float gi = fmaf(0.5f, tanha(zi), 0.5f);
        const float gf = fmaf(0.5f, tanha(zf), 0.5f);
        const float gg = tanha(zg);
        const float go = fmaf(0.5f, tanha(zo), 0.5f);

        cc = fmaf(gf, cc, gi * gg);
        h  = go * tanha(cc);

        if (dt >= 0 && wr) soB[warp][e * CSTRIDE + dt * 6 + k] = h;
    };

    // ---- prologue: stage chunk 0; step 0 computes layer0(t=0) ----
    stage(0, 0);
    __syncwarp();
    step(sx_u[0] + e * 416, -1);
    if (l) { h = 0.0f; cc = 0.0f; }   // layer1 hasn't run a real step

    // ---- main loop: chunk c covers steps m = c*16+1 .. c*16+16 ----
    for (int c = 0; c < NCHUNK; c++) {
        if (c + 1 < NCHUNK) stage(c + 1, (c + 1) & 1);
        __syncwarp();

        const uint32_t xb = sx_u[c & 1] + e * 416;
        const uint32_t xn = sx_u[(c + 1) & 1] + e * 416;

#pragma unroll
        for (int dt = 0; dt < TCHUNK; dt++) {
            // layer0 computes t = c*16 + dt + 1 -> input x(t); last reads next chunk
            const uint32_t ia = (dt < TCHUNK - 1) ? (xb + (dt + 1) * 24) : xn;
            step(ia, dt);
        }
        __syncwarp();

        // ---- flush h1 outputs for t in [c*16, c*16+16) ----
        {
            const float4* src = reinterpret_cast<const float4*>(soB[warp]);
#pragma unroll
            for (int i = 0; i < 2; i++) {
                int idx = i * 32 + lane;
                if (idx < 48) {
                    int ee  = idx / 24;
                    int off = idx - ee * 24;
                    float4* dst = reinterpret_cast<float4*>(
                        out + (size_t)(b0 + ee) * (T_LEN * 6) + c * (TCHUNK * 6));
                    dst[off] = src[ee * CSTRIDE4 + off];
                }
            }
        }
        __syncwarp();
    }
}

extern "C" void kernel_launch(void* const* d_in, const int* in_sizes, int n_in,
                              void* d_out, int out_size)
{
    const float* x    = (const float*)d_in[0];
    const float* wih0 = (const float*)d_in[1];
    const float* whh0 = (const float*)d_in[2];
    const float* bih0 = (const float*)d_in[3];
    const float* bhh0 = (const float*)d_in[4];
    const float* wih1 = (const float*)d_in[5];
    const float* whh1 = (const float*)d_in[6];
    const float* bih1 = (const float*)d_in[7];
    const float* bhh1 = (const float*)d_in[8];
    float* out = (float*)d_out;

    const int B = in_sizes[0] / (T_LEN * 6);                                 // 4096
    const int grid = (B + 2 * WARPS_PER_BLOCK - 1) / (2 * WARPS_PER_BLOCK);  // 147

    lstm2_kernel<<<grid, THREADS>>>(x, wih0, whh0, bih0, bhh0,
                                    wih1, whh1, bih1, bhh1, out, B);
}

// round 11
// speedup vs baseline: 1.0537x; 1.0537x over previous
#include <cuda_runtime.h>
#include <cstdint>

// 2-layer LSTM, H=6, F=6, B=4096, T=1024.
// 8 elements per warp, 4 lanes per element: lane = (e, l, half).
// Each lane owns hidden indices {3*half..3*half+2} of layer l: 12 gate rows,
// K-packed f32x2 (72 fma2/step). Cell chains fully lane-local.
// h-exchange per step: 3 shfl.xor(1) (partner half) + 6 idx-shfl (h0 from
// lane e*4). Weight-column permutation at load time makes the recurrent
// operand pairs (hA,hB),(hC,pA),(pB,pC) correct for BOTH halves -> no
// runtime repacking of rec operands. No per-step syncwarp.
// 512 warps as 128 blocks x 128 threads -> exactly 1 warp/SMSP on 128 SMs.
// Pipelined: main step m computes layer0(t=m) and layer1(t=m-1).
// Activations: tanh.approx; sigmoid = 0.5*tanh(z/2)+0.5 folded into weights.

#define WPB 4
#define THREADS 128
#define T_LEN 1024
#define TCHUNK 16
#define NCHUNK (T_LEN / TCHUNK)     // 64
#define XSTR 100                    // floats per elem per chunk (96 data + 4 pad)
#define SO_FLOATS 1200              // 800 data + scratch

typedef unsigned long long ull;

__device__ __forceinline__ float tanha(float x) {
    float y; asm("tanh.approx.f32 %0, %1;" : "=f"(y) : "f"(x)); return y;
}
__device__ __forceinline__ ull pk2(float lo, float hi) {
    ull r; asm("mov.b64 %0, {%1, %2};" : "=l"(r) : "f"(lo), "f"(hi)); return r;
}
__device__ __forceinline__ void upk2(float& lo, float& hi, ull v) {
    asm("mov.b64 {%0, %1}, %2;" : "=f"(lo), "=f"(hi) : "l"(v));
}
__device__ __forceinline__ ull fma2(ull a, ull b, ull c) {
    ull d; asm("fma.rn.f32x2 %0, %1, %2, %3;" : "=l"(d) : "l"(a), "l"(b), "l"(c));
    return d;
}
__device__ __forceinline__ ull mul2(ull a, ull b) {
    ull d; asm("mul.rn.f32x2 %0, %1, %2;" : "=l"(d) : "l"(a), "l"(b));
    return d;
}
__device__ __forceinline__ ull lds64(uint32_t addr) {
    ull v; asm volatile("ld.shared.b64 %0, [%1];" : "=l"(v) : "r"(addr));
    return v;
}
__device__ __forceinline__ void sts32(uint32_t addr, float v) {
    asm volatile("st.shared.f32 [%0], %1;" :: "r"(addr), "f"(v) : "memory");
}

__global__ __launch_bounds__(THREADS, 1)
void lstm2_kernel(const float* __restrict__ x,
                  const float* __restrict__ wih0, const float* __restrict__ whh0,
                  const float* __restrict__ bih0, const float* __restrict__ bhh0,
                  const float* __restrict__ wih1, const float* __restrict__ whh1,
                  const float* __restrict__ bih1, const float* __restrict__ bhh1,
                  float* __restrict__ out, int B)
{
    __shared__ float sx[2][WPB][8 * XSTR];     // x staging, double-buffered
    __shared__ float soB[WPB][SO_FLOATS];      // h1 output staging + scratch

    const int lane = threadIdx.x & 31;
    const int warp = threadIdx.x >> 5;
    const int e    = lane >> 2;        // element (0..7)
    const int sub  = lane & 3;
    const int l    = sub >> 1;         // layer
    const int half = sub & 1;          // hidden half: owns k = 3*half..3*half+2
    const int e4   = lane & 28;        // lane holding (e, l=0, half=0)

    const int b0 = (blockIdx.x * WPB + warp) * 8;
    if (b0 >= B) return;

    // ---- per-lane weights: 12 rows (4 gates x 3 hidden), K-packed ----
    const float* wihp = l ? wih1 : wih0;
    const float* whhp = l ? whh1 : whh0;
    const float* bihp = l ? bih1 : bih0;
    const float* bhhp = l ? bhh1 : bhh0;

    ull wx[12][3], wh[12][3];
    float bs[12];
#pragma unroll
    for (int g = 0; g < 4; g++) {
        const float sc = (g == 2) ? 1.0f : 0.5f;
#pragma unroll
        for (int m = 0; m < 3; m++) {
            const int row = g * 6 + 3 * half + m;
            const int r = g * 3 + m;
#pragma unroll
            for (int p = 0; p < 3; p++) {
                // v (input) pairs: natural column order
                wx[r][p] = pk2(wihp[row * 6 + 2 * p] * sc,
                               wihp[row * 6 + 2 * p + 1] * sc);
                // rec pairs arrive as (hA,hB),(hC,pA),(pB,pC):
                // half=0 -> cols (0,1),(2,3),(4,5); half=1 -> (3,4),(5,0),(1,2)
                const int ca = half ? ((2 * p + 3) % 6) : (2 * p);
                const int cb = half ? ((2 * p + 4) % 6) : (2 * p + 1);
                wh[r][p] = pk2(whhp[row * 6 + ca] * sc,
                               whhp[row * 6 + cb] * sc);
            }
            bs[r] = (bihp[row] + bhhp[row]) * sc;
        }
    }

    float hA = 0.0f, hB = 0.0f, hC = 0.0f;
    float ccA = 0.0f, ccB = 0.0f, ccC = 0.0f;

    // ---- smem addresses ----
    uint32_t sx_u[2];
    sx_u[0] = (uint32_t)__cvta_generic_to_shared(&sx[0][warp][0]);
    sx_u[1] = (uint32_t)__cvta_generic_to_shared(&sx[1][warp][0]);
    const uint32_t so_u = (uint32_t)__cvta_generic_to_shared(&soB[warp][0]);
    const uint32_t xoff = e * XSTR * 4;
    // l=1 lanes store h1 at (e*100 + 3*half)*4 + dt*24 + m*4; l=0 -> scratch
    const uint32_t so_base = l ? (so_u + e * 400 + half * 12) : (so_u + 3204);
    const uint32_t so_scr  = so_u + 3204;

    auto stage = [&](int c, int buf) {
        float4* dst = reinterpret_cast<float4*>(sx[buf][warp]);
#pragma unroll
        for (int i = 0; i < 6; i++) {
            int idx = i * 32 + lane;            // 0..191
            int ee  = idx / 24;
            int off = idx - ee * 24;
            const float4* src = reinterpret_cast<const float4*>(
                x + (size_t)(b0 + ee) * (T_LEN * 6) + c * (TCHUNK * 6));
            dst[ee * (XSTR / 4) + off] = src[off];
        }
    };

    // one step: xaddr = smem addr of 6 x floats (layer0 input), soaddr = h1 store
    auto step = [&](uint32_t xaddr, uint32_t soaddr) {
        const ull xp0 = lds64(xaddr), xp1 = lds64(xaddr + 8), xp2 = lds64(xaddr + 16);

        // exchange previous-step h
        const float pA = __shfl_xor_sync(0xffffffffu, hA, 1);
        const float pB = __shfl_xor_sync(0xffffffffu, hB, 1);
        const float pC = __shfl_xor_sync(0xffffffffu, hC, 1);
        const float t0 = __shfl_sync(0xffffffffu, hA, e4);
        const float t1 = __shfl_sync(0xffffffffu, hB, e4);
        const float t2 = __shfl_sync(0xffffffffu, hC, e4);
        const float t3 = __shfl_sync(0xffffffffu, pA, e4);
        const float t4 = __shfl_sync(0xffffffffu, pB, e4);
        const float t5 = __shfl_sync(0xffffffffu, pC, e4);

        // rec pairs (own layer), order matched by wh column permutation
        const ull rp0 = pk2(hA, hB), rp1 = pk2(hC, pA), rp2 = pk2(pB, pC);
        // v pairs: layer1 uses h0 (natural order), layer0 uses x
        const ull vp0 = l ? pk2(t0, t1) : xp0;
        const ull vp1 = l ? pk2(t2, t3) : xp1;
        const ull vp2 = l ? pk2(t4, t5) : xp2;

        ull z[12];
#pragma unroll
        for (int r = 0; r < 12; r++) z[r] = mul2(wx[r][0], vp0);
#pragma unroll
        for (int r = 0; r < 12; r++) z[r] = fma2(wx[r][1], vp1, z[r]);
#pragma unroll
        for (int r = 0; r < 12; r++) z[r] = fma2(wx[r][2], vp2, z[r]);
#pragma unroll
        for (int r = 0; r < 12; r++) z[r] = fma2(wh[r][0], rp0, z[r]);
#pragma unroll
        for (int r = 0; r < 12; r++) z[r] = fma2(wh[r][1], rp1, z[r]);
#pragma unroll
        for (int r = 0; r < 12; r++) z[r] = fma2(wh[r][2], rp2, z[r]);

#pragma unroll
        for (int m = 0; m < 3; m++) {
            float a, b;
            upk2(a, b, z[m]);     const float zi = (a + b) + bs[m];
            upk2(a, b, z[3 + m]); const float zf = (a + b) + bs[3 + m];
            upk2(a, b, z[6 + m]); const float zg = (a + b) + bs[6 + m];
            upk2(a, b, z[9 + m]); const float zo = (a + b) + bs[9 + m];

            const float gi = fmaf(0.5f, tanha(zi), 0.5f);
            const float gf = fmaf(0.5f, tanha(zf), 0.5f);
            const float gg = tanha(zg);
            const float go = fmaf(0.5f, tanha(zo), 0.5f);

            float& cm = (m == 0) ? ccA : ((m == 1) ? ccB : ccC);
            cm = fmaf(gf, cm, gi * gg);
            const float hn = go * tanha(cm);
            ((m == 0) ? hA : ((m == 1) ? hB : hC)) = hn;
            sts32(soaddr + m * 4, hn);
        }
    };

    // ---- prologue: stage chunk 0; step 0 = layer0(t=0); reset layer1 ----
    stage(0, 0);
    __syncwarp();
    step(sx_u[0] + xoff, so_scr);
    if (l) { hA = 0.0f; hB = 0.0f; hC = 0.0f; ccA = 0.0f; ccB = 0.0f; ccC = 0.0f; }

    // ---- main loop: chunk c covers steps m = c*16+1 .. c*16+16 ----
    for (int c = 0; c < NCHUNK; c++) {
        if (c + 1 < NCHUNK) stage(c + 1, (c + 1) & 1);
        __syncwarp();

        const uint32_t xb = sx_u[c & 1] + xoff;
        const uint32_t xn = sx_u[(c + 1) & 1] + xoff;

#pragma unroll 4
        for (int dt = 0; dt < TCHUNK; dt++) {
            const uint32_t ia = (dt < TCHUNK - 1) ? (xb + (dt + 1) * 24) : xn;
            step(ia, so_base + dt * 24);
        }
        __syncwarp();

        // ---- flush h1 outputs for t in [c*16, c*16+16) ----
        {
            const float4* src = reinterpret_cast<const float4*>(&soB[warp][0]);
#pragma unroll
            for (int i = 0; i < 6; i++) {
                int idx = i * 32 + lane;        // 0..191
                int ee  = idx / 24;
                int off = idx - ee * 24;
                float4* dst = reinterpret_cast<float4*>(
                    out + (size_t)(b0 + ee) * (T_LEN * 6) + c * (TCHUNK * 6));
                dst[off] = src[ee * (XSTR / 4) + off];
            }
        }
        __syncwarp();
    }
}

extern "C" void kernel_launch(void* const* d_in, const int* in_sizes, int n_in,
                              void* d_out, int out_size)
{
    const float* x    = (const float*)d_in[0];
    const float* wih0 = (const float*)d_in[1];
    const float* whh0 = (const float*)d_in[2];
    const float* bih0 = (const float*)d_in[3];
    const float* bhh0 = (const float*)d_in[4];
    const float* wih1 = (const float*)d_in[5];
    const float* whh1 = (const float*)d_in[6];
    const float* bih1 = (const float*)d_in[7];
    const float* bhh1 = (const float*)d_in[8];
    float* out = (float*)d_out;

    const int B = in_sizes[0] / (T_LEN * 6);           // 4096
    const int grid = (B + 8 * WPB - 1) / (8 * WPB);    // 128

    lstm2_kernel<<<grid, THREADS>>>(x, wih0, whh0, bih0, bhh0,
                                    wih1, whh1, bih1, bhh1, out, B);
}